// round 2
// baseline (speedup 1.0000x reference)
#include <cuda_runtime.h>
#include <math.h>
#include <float.h>

#define NN 50000
#define EE 640000
#define NB_SCAN 98   // ceil(NN/512)

// ---------------- scratch (device globals; no allocation allowed) ----------
__device__ float g_Xi[NN * 128];
__device__ float g_Xj[NN * 128];
__device__ float g_Xn[NN * 128];
__device__ float g_agg[NN * 128];
__device__ float g_hid[NN * 128];
__device__ float g_e[EE * 2];
__device__ float g_T[49 * 128];     // T1[35] | T2[9] | Crc[2] | Crp[3]
__device__ int   g_cnt[NN];
__device__ int   g_off[NN + 1];
__device__ int   g_cur[NN];
__device__ int   g_csr[EE];
__device__ int   g_bsum[128];
__device__ unsigned g_gmax[384];

// ---------------- helpers ---------------------------------------------------
__device__ __forceinline__ float gelu_t(float x) {
    float x3 = x * x * x;
    return 0.5f * x * (1.f + tanhf(0.7978845608028654f * (x + 0.044715f * x3)));
}
__device__ __forceinline__ unsigned fenc(float f) {
    unsigned u = __float_as_uint(f);
    return (u & 0x80000000u) ? ~u : (u | 0x80000000u);
}
__device__ __forceinline__ float fdec(unsigned u) {
    return (u & 0x80000000u) ? __uint_as_float(u & 0x7fffffffu) : __uint_as_float(~u);
}

// ---------------- CSR construction ------------------------------------------
__global__ void k_csr_init() {
    int i = blockIdx.x * 256 + threadIdx.x;
    if (i < NN) g_cnt[i] = 0;
}
__global__ void k_hist(const int* __restrict__ dst) {
    int e = blockIdx.x * 256 + threadIdx.x;
    if (e < EE) atomicAdd(&g_cnt[dst[e]], 1);
}
__global__ void k_scan1() {
    __shared__ int s[512];
    int i = blockIdx.x * 512 + threadIdx.x;
    int v = (i < NN) ? g_cnt[i] : 0;
    s[threadIdx.x] = v;
    __syncthreads();
    for (int off = 1; off < 512; off <<= 1) {
        int t = (threadIdx.x >= off) ? s[threadIdx.x - off] : 0;
        __syncthreads();
        s[threadIdx.x] += t;
        __syncthreads();
    }
    if (i < NN) g_off[i] = s[threadIdx.x] - v;           // exclusive within block
    if (threadIdx.x == 511) g_bsum[blockIdx.x] = s[511];
}
__global__ void k_scan2() {
    if (threadIdx.x == 0) {
        int run = 0;
        for (int b = 0; b < NB_SCAN; b++) { int t = g_bsum[b]; g_bsum[b] = run; run += t; }
    }
}
__global__ void k_scan3() {
    int i = blockIdx.x * 256 + threadIdx.x;
    if (i < NN) {
        int v = g_off[i] + g_bsum[i >> 9];
        g_off[i] = v;
        g_cur[i] = v;
    }
    if (i == 0) g_off[NN] = EE;
}
__global__ void k_scatter(const int* __restrict__ dst) {
    int e = blockIdx.x * 256 + threadIdx.x;
    if (e < EE) {
        int p = atomicAdd(&g_cur[dst[e]], 1);
        g_csr[p] = e;
    }
}

// ---------------- generic fp32 GEMM: C = act(A@B + bias) (+res) ------------
// A[M,K] row stride lda, B[K,Nc] row-major dense, C row stride ldc.
__global__ void k_gemm(const float* __restrict__ A, int lda,
                       const float* __restrict__ B,
                       const float* __restrict__ bias,
                       const float* __restrict__ res, int ldres,
                       float* __restrict__ C, int ldc,
                       int M, int K, int Nc, int act) {
    __shared__ float As[64][33];
    __shared__ float Bs[32][128];
    int tid = threadIdx.x;
    int tx = tid & 15, ty = tid >> 4;
    int m0 = blockIdx.x * 64;
    float acc[4][8];
#pragma unroll
    for (int r = 0; r < 4; r++)
#pragma unroll
        for (int j = 0; j < 8; j++) acc[r][j] = 0.f;

    for (int kb = 0; kb < K; kb += 32) {
        int kc = K - kb; if (kc > 32) kc = 32;
#pragma unroll
        for (int i = 0; i < 8; i++) {
            int idx = tid + i * 256;
            int r = idx >> 5, k = idx & 31;
            float v = 0.f;
            int gm = m0 + r;
            if (k < kc && gm < M) v = A[(long)gm * lda + kb + k];
            As[r][k] = v;
        }
#pragma unroll
        for (int i = 0; i < 4; i++) {
            int idx = tid + i * 256;
            int k = idx >> 5, n = (idx & 31) * 4;
            float4 v = make_float4(0.f, 0.f, 0.f, 0.f);
            if (k < kc && n < Nc) v = *(const float4*)(B + (long)(kb + k) * Nc + n);
            *(float4*)&Bs[k][n] = v;
        }
        __syncthreads();
#pragma unroll 8
        for (int k = 0; k < 32; k++) {
            float a0 = As[ty * 4 + 0][k];
            float a1 = As[ty * 4 + 1][k];
            float a2 = As[ty * 4 + 2][k];
            float a3 = As[ty * 4 + 3][k];
            float4 b0 = *(float4*)&Bs[k][tx * 8];
            float4 b1 = *(float4*)&Bs[k][tx * 8 + 4];
            float bb[8] = {b0.x, b0.y, b0.z, b0.w, b1.x, b1.y, b1.z, b1.w};
#pragma unroll
            for (int j = 0; j < 8; j++) {
                acc[0][j] += a0 * bb[j];
                acc[1][j] += a1 * bb[j];
                acc[2][j] += a2 * bb[j];
                acc[3][j] += a3 * bb[j];
            }
        }
        __syncthreads();
    }
#pragma unroll
    for (int r = 0; r < 4; r++) {
        int gm = m0 + ty * 4 + r;
        if (gm >= M) continue;
#pragma unroll
        for (int j = 0; j < 8; j++) {
            int col = tx * 8 + j;
            if (col >= Nc) continue;
            float v = acc[r][j];
            if (bias) v += bias[col];
            if (act == 1) v = gelu_t(v);
            if (res) v += res[(long)gm * ldres + col];
            C[(long)gm * ldc + col] = v;
        }
    }
}

// ---------------- per-layer edge tables: (ef @ W_fij) decomposition --------
__global__ void k_tables(const float* __restrict__ type_emb, const float* __restrict__ rid_emb,
                         const float* __restrict__ rc_W, const float* __restrict__ rc_b,
                         const float* __restrict__ rp_W, const float* __restrict__ rp_b,
                         const float* __restrict__ Wf) {
    __shared__ float Ws[64 * 128];
    int tid = threadIdx.x;  // 128
    for (int i = tid; i < 64 * 128; i += 128) Ws[i] = Wf[i];
    __syncthreads();
    int d = tid;
    float b0 = 0.f;
    for (int k = 0; k < 64; k++) b0 += (rc_b[k] + rp_b[k]) * Ws[k * 128 + d];
    for (int t = 0; t < 35; t++) {
        float a = b0;
        for (int k = 0; k < 64; k++) a += type_emb[t * 64 + k] * Ws[k * 128 + d];
        g_T[t * 128 + d] = a;
    }
    for (int r = 0; r < 9; r++) {
        float a = 0.f;
        for (int k = 0; k < 64; k++) a += rid_emb[r * 64 + k] * Ws[k * 128 + d];
        g_T[(35 + r) * 128 + d] = a;
    }
    for (int j = 0; j < 2; j++) {
        float a = 0.f;
        for (int k = 0; k < 64; k++) a += rc_W[j * 64 + k] * Ws[k * 128 + d];
        g_T[(44 + j) * 128 + d] = a;
    }
    for (int j = 0; j < 3; j++) {
        float a = 0.f;
        for (int k = 0; k < 64; k++) a += rp_W[j * 64 + k] * Ws[k * 128 + d];
        g_T[(46 + j) * 128 + d] = a;
    }
}

// ---------------- edge logits: one warp per edge ----------------------------
__global__ void k_edge(const int* __restrict__ src, const int* __restrict__ dst,
                       const int* __restrict__ etype, const int* __restrict__ erid,
                       const float* __restrict__ att_rc, const float* __restrict__ att_rp,
                       const float* __restrict__ attn_l) {
    __shared__ float sT[49 * 128];
    __shared__ float sA[128];
    int tid = threadIdx.x;  // 256
    for (int i = tid; i < 49 * 128; i += 256) sT[i] = g_T[i];
    for (int i = tid; i < 128; i += 256) sA[i] = attn_l[i];
    __syncthreads();
    const float4* T1 = (const float4*)sT;
    const float4* T2 = (const float4*)(sT + 35 * 128);
    const float4* Crc = (const float4*)(sT + 44 * 128);
    const float4* Crp = (const float4*)(sT + 46 * 128);
    const float4* A4 = (const float4*)sA;
    const float4* Xi4 = (const float4*)g_Xi;
    const float4* Xj4 = (const float4*)g_Xj;
    int lane = tid & 31, wid = tid >> 5;
    float4 a4 = A4[lane];
    float4 c0 = Crc[lane], c1 = Crc[32 + lane];
    float4 p0 = Crp[lane], p1 = Crp[32 + lane], p2 = Crp[64 + lane];
    for (int e = blockIdx.x * 8 + wid; e < EE; e += gridDim.x * 8) {
        int s = __ldg(src + e), d = __ldg(dst + e);
        int et = __ldg(etype + e), er = __ldg(erid + e);
        float rc0 = __ldg(att_rc + 2 * e), rc1 = __ldg(att_rc + 2 * e + 1);
        float rp0 = __ldg(att_rp + 3 * e), rp1 = __ldg(att_rp + 3 * e + 1),
              rp2 = __ldg(att_rp + 3 * e + 2);
        float4 xi = Xi4[s * 32 + lane];
        float4 xj = Xj4[d * 32 + lane];
        float4 t1 = T1[et * 32 + lane];
        float4 t2 = T2[er * 32 + lane];
        float fx = xi.x + xj.x + t1.x + t2.x + rc0 * c0.x + rc1 * c1.x + rp0 * p0.x + rp1 * p1.x + rp2 * p2.x;
        float fy = xi.y + xj.y + t1.y + t2.y + rc0 * c0.y + rc1 * c1.y + rp0 * p0.y + rp1 * p1.y + rp2 * p2.y;
        float fz = xi.z + xj.z + t1.z + t2.z + rc0 * c0.z + rc1 * c1.z + rp0 * p0.z + rp1 * p1.z + rp2 * p2.z;
        float fw = xi.w + xj.w + t1.w + t2.w + rc0 * c0.w + rc1 * c1.w + rp0 * p0.w + rp1 * p1.w + rp2 * p2.w;
        fx = fx > 0.f ? fx : 0.2f * fx;
        fy = fy > 0.f ? fy : 0.2f * fy;
        fz = fz > 0.f ? fz : 0.2f * fz;
        fw = fw > 0.f ? fw : 0.2f * fw;
        float sd = fx * a4.x + fy * a4.y + fz * a4.z + fw * a4.w;
        sd += __shfl_xor_sync(0xffffffffu, sd, 1);
        sd += __shfl_xor_sync(0xffffffffu, sd, 2);
        sd += __shfl_xor_sync(0xffffffffu, sd, 4);
        sd += __shfl_xor_sync(0xffffffffu, sd, 8);
        if (lane == 0) g_e[2 * e] = sd;       // head 0
        if (lane == 16) g_e[2 * e + 1] = sd;  // head 1
    }
}

// ---------------- per-dst softmax + aggregate (CSR, block per dst) ---------
__global__ void k_agg(const int* __restrict__ src) {
    int dn = blockIdx.x;
    int beg = g_off[dn], end = g_off[dn + 1];
    int deg = end - beg;
    int tid = threadIdx.x;  // 128
    if (deg == 0) { g_agg[dn * 128 + tid] = 0.f; return; }
    __shared__ float red[128];
    __shared__ float sw[2][128];
    __shared__ int ssrc[128];
    float m0 = -FLT_MAX, m1 = -FLT_MAX;
    for (int i = tid; i < deg; i += 128) {
        int eid = g_csr[beg + i];
        m0 = fmaxf(m0, g_e[2 * eid]);
        m1 = fmaxf(m1, g_e[2 * eid + 1]);
    }
    red[tid] = m0; __syncthreads();
    for (int s = 64; s > 0; s >>= 1) { if (tid < s) red[tid] = fmaxf(red[tid], red[tid + s]); __syncthreads(); }
    m0 = red[0]; __syncthreads();
    red[tid] = m1; __syncthreads();
    for (int s = 64; s > 0; s >>= 1) { if (tid < s) red[tid] = fmaxf(red[tid], red[tid + s]); __syncthreads(); }
    m1 = red[0]; __syncthreads();
    float z0 = 0.f, z1 = 0.f;
    for (int i = tid; i < deg; i += 128) {
        int eid = g_csr[beg + i];
        z0 += __expf(g_e[2 * eid] - m0);
        z1 += __expf(g_e[2 * eid + 1] - m1);
    }
    red[tid] = z0; __syncthreads();
    for (int s = 64; s > 0; s >>= 1) { if (tid < s) red[tid] += red[tid + s]; __syncthreads(); }
    z0 = red[0]; __syncthreads();
    red[tid] = z1; __syncthreads();
    for (int s = 64; s > 0; s >>= 1) { if (tid < s) red[tid] += red[tid + s]; __syncthreads(); }
    z1 = red[0]; __syncthreads();
    float acc = 0.f;
    int h = tid >> 6;
    for (int cs = 0; cs < deg; cs += 128) {
        int cnt = min(128, deg - cs);
        if (tid < cnt) {
            int eid = g_csr[beg + cs + tid];
            ssrc[tid] = src[eid];
            sw[0][tid] = __expf(g_e[2 * eid] - m0);
            sw[1][tid] = __expf(g_e[2 * eid + 1] - m1);
        }
        __syncthreads();
        for (int i = 0; i < cnt; i++)
            acc += g_Xn[(long)ssrc[i] * 128 + tid] * sw[h][i];
        __syncthreads();
    }
    g_agg[dn * 128 + tid] = acc / (h ? z1 : z0);
}

// ---------------- output assembly -------------------------------------------
__global__ void k_featcopy(const float* __restrict__ feat, float* __restrict__ out) {
    int i = blockIdx.x * 256 + threadIdx.x;
    if (i < NN * 32) {
        int r = i >> 5, c = i & 31;
        out[(long)r * 704 + c] = feat[i];
    }
}
__global__ void k_gmax_init() {
    int i = blockIdx.x * blockDim.x + threadIdx.x;
    if (i < 352) g_gmax[i] = fenc(-FLT_MAX);
}
__global__ void k_colmax(const float* __restrict__ out) {
    int col = blockIdx.y * 128 + threadIdx.x;
    if (col >= 352) return;
    int r0 = blockIdx.x * 512;
    int r1 = min(NN, r0 + 512);
    float m = -FLT_MAX;
    for (int r = r0; r < r1; r++) m = fmaxf(m, out[(long)r * 704 + col]);
    atomicMax(&g_gmax[col], fenc(m));
}
__global__ void k_bcast(float* __restrict__ out) {
    int i = blockIdx.x * 256 + threadIdx.x;
    if (i < NN * 352) {
        int r = i / 352, c = i - r * 352;
        out[(long)r * 704 + 352 + c] = fdec(g_gmax[c]);
    }
}

// ---------------- host driver ------------------------------------------------
extern "C" void kernel_launch(void* const* d_in, const int* in_sizes, int n_in,
                              void* d_out, int out_size) {
    const float* feat    = (const float*)d_in[0];
    const float* att_rc  = (const float*)d_in[1];
    const float* att_rp  = (const float*)d_in[2];
    const float* type_emb= (const float*)d_in[3];
    const float* rid_emb = (const float*)d_in[4];
    const float* rc_W    = (const float*)d_in[5];
    const float* rc_b    = (const float*)d_in[6];
    const float* rp_W    = (const float*)d_in[7];
    const float* rp_b    = (const float*)d_in[8];
    const float* fe_W1   = (const float*)d_in[9];
    const float* fe_b1   = (const float*)d_in[10];
    const float* fe_W2   = (const float*)d_in[11];
    const float* fe_b2   = (const float*)d_in[12];
    const float* W_ni    = (const float*)d_in[13];
    const float* W_nj    = (const float*)d_in[14];
    const float* W_fij   = (const float*)d_in[15];
    const float* W_node  = (const float*)d_in[16];
    const float* b_node  = (const float*)d_in[17];
    const float* attn    = (const float*)d_in[18];
    const float* mlp_W1  = (const float*)d_in[19];
    const float* mlp_b1  = (const float*)d_in[20];
    const float* mlp_W2  = (const float*)d_in[21];
    const float* mlp_b2  = (const float*)d_in[22];
    const int* src   = (const int*)d_in[23];
    const int* dst   = (const int*)d_in[24];
    const int* etype = (const int*)d_in[25];
    const int* erid  = (const int*)d_in[26];
    float* out = (float*)d_out;

    float *pXi, *pXj, *pXn, *pAgg, *pHid;
    cudaGetSymbolAddress((void**)&pXi, g_Xi);
    cudaGetSymbolAddress((void**)&pXj, g_Xj);
    cudaGetSymbolAddress((void**)&pXn, g_Xn);
    cudaGetSymbolAddress((void**)&pAgg, g_agg);
    cudaGetSymbolAddress((void**)&pHid, g_hid);

    // CSR by dst (rebuilt every call; deterministic work)
    k_csr_init<<<(NN + 255) / 256, 256>>>();
    k_hist<<<(EE + 255) / 256, 256>>>(dst);
    k_scan1<<<NB_SCAN, 512>>>();
    k_scan2<<<1, 32>>>();
    k_scan3<<<(NN + 255) / 256, 256>>>();
    k_scatter<<<(EE + 255) / 256, 256>>>(dst);

    // output cols [0,32) = feat
    k_featcopy<<<(NN * 32 + 255) / 256, 256>>>(feat, out);

    int gm = (NN + 63) / 64;
    // feature-encoder MLP -> h0 at cols [32,96)
    k_gemm<<<gm, 256>>>(feat, 32, fe_W1, fe_b1, nullptr, 0, pHid, 64, NN, 32, 64, 1);
    k_gemm<<<gm, 256>>>(pHid, 64, fe_W2, fe_b2, nullptr, 0, out + 32, 704, NN, 64, 64, 0);

    for (int l = 0; l < 4; l++) {
        const float* h = out + 32 + 64 * l;  // current h, row stride 704
        k_gemm<<<gm, 256>>>(h, 704, W_ni + l * 64 * 128, nullptr, nullptr, 0, pXi, 128, NN, 64, 128, 0);
        k_gemm<<<gm, 256>>>(h, 704, W_nj + l * 64 * 128, nullptr, nullptr, 0, pXj, 128, NN, 64, 128, 0);
        k_gemm<<<gm, 256>>>(h, 704, W_node + l * 64 * 128, b_node + l * 128, nullptr, 0, pXn, 128, NN, 64, 128, 0);
        k_tables<<<1, 128>>>(type_emb, rid_emb, rc_W, rc_b, rp_W, rp_b, W_fij + l * 64 * 128);
        k_edge<<<2048, 256>>>(src, dst, etype, erid, att_rc, att_rp, attn + l * 128);
        k_agg<<<NN, 128>>>(src);
        k_gemm<<<gm, 256>>>(pAgg, 128, mlp_W1 + l * 128 * 128, mlp_b1 + l * 128, nullptr, 0, pHid, 128, NN, 128, 128, 1);
        k_gemm<<<gm, 256>>>(pHid, 128, mlp_W2 + l * 128 * 64, mlp_b2 + l * 64, h, 704,
                            out + 32 + 64 * (l + 1), 704, NN, 128, 64, 0);
    }

    // graph max pooling over node_emb (cols [0,352)) -> broadcast to cols [352,704)
    k_gmax_init<<<2, 256>>>();
    dim3 gcm((NN + 511) / 512, 3);
    k_colmax<<<gcm, 128>>>(out);
    k_bcast<<<(NN * 352 + 255) / 256, 256>>>(out);
}

// round 3
// speedup vs baseline: 1.3362x; 1.3362x over previous
#include <cuda_runtime.h>
#include <math.h>
#include <float.h>

#define NN 50000
#define EE 640000
#define NB_SCAN 98   // ceil(NN/512)

// ---------------- scratch (device globals; no allocation allowed) ----------
__device__ float g_Xi[NN * 128];
__device__ float g_Xj[NN * 128];
__device__ float g_Xn[NN * 128];
__device__ float g_agg[NN * 128];
__device__ float g_hid[NN * 128];
__device__ float g_hbuf[NN * 64];
__device__ float g_e[EE * 2];
__device__ float g_T[49 * 128];     // T1[35] | T2[9] | Crc[2] | Crp[3]
__device__ int   g_cnt[NN];
__device__ int   g_off[NN + 1];
__device__ int   g_cur[NN];
__device__ int   g_csr[EE];
__device__ int   g_bsum[128];
__device__ unsigned g_gmax[384];

// ---------------- helpers ---------------------------------------------------
__device__ __forceinline__ float gelu_t(float x) {
    float x3 = x * x * x;
    return 0.5f * x * (1.f + tanhf(0.7978845608028654f * (x + 0.044715f * x3)));
}
__device__ __forceinline__ unsigned fenc(float f) {
    unsigned u = __float_as_uint(f);
    return (u & 0x80000000u) ? ~u : (u | 0x80000000u);
}
__device__ __forceinline__ float fdec(unsigned u) {
    return (u & 0x80000000u) ? __uint_as_float(u & 0x7fffffffu) : __uint_as_float(~u);
}

// ---------------- CSR construction ------------------------------------------
__global__ void k_csr_init() {
    int i = blockIdx.x * 256 + threadIdx.x;
    if (i < NN) g_cnt[i] = 0;
}
__global__ void k_hist(const int* __restrict__ dst) {
    int e = blockIdx.x * 256 + threadIdx.x;
    if (e < EE) atomicAdd(&g_cnt[dst[e]], 1);
}
__global__ void k_scan1() {
    __shared__ int s[512];
    int i = blockIdx.x * 512 + threadIdx.x;
    int v = (i < NN) ? g_cnt[i] : 0;
    s[threadIdx.x] = v;
    __syncthreads();
    for (int off = 1; off < 512; off <<= 1) {
        int t = (threadIdx.x >= off) ? s[threadIdx.x - off] : 0;
        __syncthreads();
        s[threadIdx.x] += t;
        __syncthreads();
    }
    if (i < NN) g_off[i] = s[threadIdx.x] - v;
    if (threadIdx.x == 511) g_bsum[blockIdx.x] = s[511];
}
__global__ void k_scan2() {
    if (threadIdx.x == 0) {
        int run = 0;
        for (int b = 0; b < NB_SCAN; b++) { int t = g_bsum[b]; g_bsum[b] = run; run += t; }
    }
}
__global__ void k_scan3() {
    int i = blockIdx.x * 256 + threadIdx.x;
    if (i < NN) {
        int v = g_off[i] + g_bsum[i >> 9];
        g_off[i] = v;
        g_cur[i] = v;
    }
    if (i == 0) g_off[NN] = EE;
}
__global__ void k_scatter(const int* __restrict__ dst) {
    int e = blockIdx.x * 256 + threadIdx.x;
    if (e < EE) {
        int p = atomicAdd(&g_cur[dst[e]], 1);
        g_csr[p] = e;
    }
}

// ---------------- double-buffered SGEMM -------------------------------------
// C[M,BN] = act(A[M,K] @ B[K,BN] + bias) (+res), optional dual output C2.
// 8x8 micro-tile in split-strip layout; BK=8; 128 threads.
template<int BM, int BN, int NA, int NB>
__device__ __forceinline__ void gload(const float* __restrict__ A, int lda,
                                      const float* __restrict__ B,
                                      int m0, int kb, int M, int tid,
                                      float4* ra, float4* rb) {
    constexpr int TH = (BM / 8) * (BN / 8);
#pragma unroll
    for (int i = 0; i < NA; i++) {
        int s = tid + i * TH;
        int ar = s / 2;            // BK/4 == 2
        int ak = (s & 1) * 4;
        int gm = m0 + ar;
        if (gm < M) ra[i] = *(const float4*)(A + (long)gm * lda + kb + ak);
        else        ra[i] = make_float4(0.f, 0.f, 0.f, 0.f);
    }
#pragma unroll
    for (int i = 0; i < NB; i++) {
        int s = tid + i * TH;
        int br = s / (BN / 4);
        int bc = (s % (BN / 4)) * 4;
        rb[i] = *(const float4*)(B + (long)(kb + br) * BN + bc);
    }
}

template<int BM, int BN>
__global__ __launch_bounds__((BM / 8) * (BN / 8), 4)
void k_gemm_t(const float* __restrict__ A, int lda,
              const float* __restrict__ B,
              const float* __restrict__ bias,
              const float* __restrict__ res, int ldres,
              float* __restrict__ C, int ldc,
              float* __restrict__ C2, int ldc2,
              int M, int K, int act) {
    constexpr int BK = 8;
    constexpr int TH = (BM / 8) * (BN / 8);
    constexpr int NA = BM * BK / 4 / TH;
    constexpr int NB = BK * BN / 4 / TH;
    __shared__ float As[2][BK][BM];
    __shared__ float Bs[2][BK][BN];
    const int tid = threadIdx.x;
    const int tx = tid % (BN / 8);
    const int ty = tid / (BN / 8);
    const int m0 = blockIdx.x * BM;

    float4 ra[NA], rb[NB];
    float acc[8][8];
#pragma unroll
    for (int i = 0; i < 8; i++)
#pragma unroll
        for (int j = 0; j < 8; j++) acc[i][j] = 0.f;

    gload<BM, BN, NA, NB>(A, lda, B, m0, 0, M, tid, ra, rb);
    {
#pragma unroll
        for (int i = 0; i < NA; i++) {
            int s = tid + i * TH;
            int ar = s / 2, ak = (s & 1) * 4;
            As[0][ak + 0][ar] = ra[i].x; As[0][ak + 1][ar] = ra[i].y;
            As[0][ak + 2][ar] = ra[i].z; As[0][ak + 3][ar] = ra[i].w;
        }
#pragma unroll
        for (int i = 0; i < NB; i++) {
            int s = tid + i * TH;
            int br = s / (BN / 4), bc = (s % (BN / 4)) * 4;
            *(float4*)&Bs[0][br][bc] = rb[i];
        }
    }
    __syncthreads();

    const int nk = K / BK;
    int buf = 0;
    for (int it = 0; it < nk; it++) {
        if (it + 1 < nk)
            gload<BM, BN, NA, NB>(A, lda, B, m0, (it + 1) * BK, M, tid, ra, rb);
#pragma unroll
        for (int k = 0; k < BK; k++) {
            float4 a0 = *(const float4*)&As[buf][k][ty * 4];
            float4 a1 = *(const float4*)&As[buf][k][BM / 2 + ty * 4];
            float4 b0 = *(const float4*)&Bs[buf][k][tx * 4];
            float4 b1 = *(const float4*)&Bs[buf][k][BN / 2 + tx * 4];
            float av[8] = {a0.x, a0.y, a0.z, a0.w, a1.x, a1.y, a1.z, a1.w};
            float bv[8] = {b0.x, b0.y, b0.z, b0.w, b1.x, b1.y, b1.z, b1.w};
#pragma unroll
            for (int i = 0; i < 8; i++)
#pragma unroll
                for (int j = 0; j < 8; j++)
                    acc[i][j] += av[i] * bv[j];
        }
        if (it + 1 < nk) {
            int nb2 = buf ^ 1;
#pragma unroll
            for (int i = 0; i < NA; i++) {
                int s = tid + i * TH;
                int ar = s / 2, ak = (s & 1) * 4;
                As[nb2][ak + 0][ar] = ra[i].x; As[nb2][ak + 1][ar] = ra[i].y;
                As[nb2][ak + 2][ar] = ra[i].z; As[nb2][ak + 3][ar] = ra[i].w;
            }
#pragma unroll
            for (int i = 0; i < NB; i++) {
                int s = tid + i * TH;
                int br = s / (BN / 4), bc = (s % (BN / 4)) * 4;
                *(float4*)&Bs[nb2][br][bc] = rb[i];
            }
            __syncthreads();
            buf = nb2;
        }
    }

#pragma unroll
    for (int i = 0; i < 8; i++) {
        int gm = m0 + ((i < 4) ? (ty * 4 + i) : (BM / 2 + ty * 4 + i - 4));
        if (gm >= M) continue;
#pragma unroll
        for (int cg = 0; cg < 2; cg++) {
            int col = cg ? (BN / 2 + tx * 4) : (tx * 4);
            float v0 = acc[i][cg * 4 + 0];
            float v1 = acc[i][cg * 4 + 1];
            float v2 = acc[i][cg * 4 + 2];
            float v3 = acc[i][cg * 4 + 3];
            if (bias) {
                float4 bb = *(const float4*)(bias + col);
                v0 += bb.x; v1 += bb.y; v2 += bb.z; v3 += bb.w;
            }
            if (act) {
                v0 = gelu_t(v0); v1 = gelu_t(v1); v2 = gelu_t(v2); v3 = gelu_t(v3);
            }
            if (res) {
                float4 rr = *(const float4*)(res + (long)gm * ldres + col);
                v0 += rr.x; v1 += rr.y; v2 += rr.z; v3 += rr.w;
            }
            float4 v = make_float4(v0, v1, v2, v3);
            *(float4*)(C + (long)gm * ldc + col) = v;
            if (C2) *(float4*)(C2 + (long)gm * ldc2 + col) = v;
        }
    }
}

// ---------------- per-layer edge tables: (ef @ W_fij) decomposition --------
__global__ void k_tables(const float* __restrict__ type_emb, const float* __restrict__ rid_emb,
                         const float* __restrict__ rc_W, const float* __restrict__ rc_b,
                         const float* __restrict__ rp_W, const float* __restrict__ rp_b,
                         const float* __restrict__ Wf) {
    __shared__ float Ws[64 * 128];
    int tid = threadIdx.x;  // 128
    for (int i = tid; i < 64 * 128; i += 128) Ws[i] = Wf[i];
    __syncthreads();
    int d = tid;
    float b0 = 0.f;
    for (int k = 0; k < 64; k++) b0 += (rc_b[k] + rp_b[k]) * Ws[k * 128 + d];
    for (int t = 0; t < 35; t++) {
        float a = b0;
        for (int k = 0; k < 64; k++) a += type_emb[t * 64 + k] * Ws[k * 128 + d];
        g_T[t * 128 + d] = a;
    }
    for (int r = 0; r < 9; r++) {
        float a = 0.f;
        for (int k = 0; k < 64; k++) a += rid_emb[r * 64 + k] * Ws[k * 128 + d];
        g_T[(35 + r) * 128 + d] = a;
    }
    for (int j = 0; j < 2; j++) {
        float a = 0.f;
        for (int k = 0; k < 64; k++) a += rc_W[j * 64 + k] * Ws[k * 128 + d];
        g_T[(44 + j) * 128 + d] = a;
    }
    for (int j = 0; j < 3; j++) {
        float a = 0.f;
        for (int k = 0; k < 64; k++) a += rp_W[j * 64 + k] * Ws[k * 128 + d];
        g_T[(46 + j) * 128 + d] = a;
    }
}

// ---------------- edge logits: one warp per edge ----------------------------
__global__ void k_edge(const int* __restrict__ src, const int* __restrict__ dst,
                       const int* __restrict__ etype, const int* __restrict__ erid,
                       const float* __restrict__ att_rc, const float* __restrict__ att_rp,
                       const float* __restrict__ attn_l) {
    __shared__ float sT[49 * 128];
    __shared__ float sA[128];
    int tid = threadIdx.x;  // 256
    for (int i = tid; i < 49 * 128; i += 256) sT[i] = g_T[i];
    for (int i = tid; i < 128; i += 256) sA[i] = attn_l[i];
    __syncthreads();
    const float4* T1 = (const float4*)sT;
    const float4* T2 = (const float4*)(sT + 35 * 128);
    const float4* Crc = (const float4*)(sT + 44 * 128);
    const float4* Crp = (const float4*)(sT + 46 * 128);
    const float4* A4 = (const float4*)sA;
    const float4* Xi4 = (const float4*)g_Xi;
    const float4* Xj4 = (const float4*)g_Xj;
    int lane = tid & 31, wid = tid >> 5;
    float4 a4 = A4[lane];
    float4 c0 = Crc[lane], c1 = Crc[32 + lane];
    float4 p0 = Crp[lane], p1 = Crp[32 + lane], p2 = Crp[64 + lane];
    for (int e = blockIdx.x * 8 + wid; e < EE; e += gridDim.x * 8) {
        int s = __ldg(src + e), d = __ldg(dst + e);
        int et = __ldg(etype + e), er = __ldg(erid + e);
        float rc0 = __ldg(att_rc + 2 * e), rc1 = __ldg(att_rc + 2 * e + 1);
        float rp0 = __ldg(att_rp + 3 * e), rp1 = __ldg(att_rp + 3 * e + 1),
              rp2 = __ldg(att_rp + 3 * e + 2);
        float4 xi = Xi4[s * 32 + lane];
        float4 xj = Xj4[d * 32 + lane];
        float4 t1 = T1[et * 32 + lane];
        float4 t2 = T2[er * 32 + lane];
        float fx = xi.x + xj.x + t1.x + t2.x + rc0 * c0.x + rc1 * c1.x + rp0 * p0.x + rp1 * p1.x + rp2 * p2.x;
        float fy = xi.y + xj.y + t1.y + t2.y + rc0 * c0.y + rc1 * c1.y + rp0 * p0.y + rp1 * p1.y + rp2 * p2.y;
        float fz = xi.z + xj.z + t1.z + t2.z + rc0 * c0.z + rc1 * c1.z + rp0 * p0.z + rp1 * p1.z + rp2 * p2.z;
        float fw = xi.w + xj.w + t1.w + t2.w + rc0 * c0.w + rc1 * c1.w + rp0 * p0.w + rp1 * p1.w + rp2 * p2.w;
        fx = fx > 0.f ? fx : 0.2f * fx;
        fy = fy > 0.f ? fy : 0.2f * fy;
        fz = fz > 0.f ? fz : 0.2f * fz;
        fw = fw > 0.f ? fw : 0.2f * fw;
        float sd = fx * a4.x + fy * a4.y + fz * a4.z + fw * a4.w;
        sd += __shfl_xor_sync(0xffffffffu, sd, 1);
        sd += __shfl_xor_sync(0xffffffffu, sd, 2);
        sd += __shfl_xor_sync(0xffffffffu, sd, 4);
        sd += __shfl_xor_sync(0xffffffffu, sd, 8);
        if (lane == 0) g_e[2 * e] = sd;       // head 0
        if (lane == 16) g_e[2 * e + 1] = sd;  // head 1
    }
}

// ---------------- per-dst softmax + aggregate (CSR, block per dst) ---------
__global__ void k_agg(const int* __restrict__ src) {
    int dn = blockIdx.x;
    int beg = g_off[dn], end = g_off[dn + 1];
    int deg = end - beg;
    int tid = threadIdx.x;  // 128
    if (deg == 0) { g_agg[dn * 128 + tid] = 0.f; return; }
    __shared__ float red[128];
    __shared__ float sw[2][128];
    __shared__ int ssrc[128];
    float m0 = -FLT_MAX, m1 = -FLT_MAX;
    for (int i = tid; i < deg; i += 128) {
        int eid = g_csr[beg + i];
        m0 = fmaxf(m0, g_e[2 * eid]);
        m1 = fmaxf(m1, g_e[2 * eid + 1]);
    }
    red[tid] = m0; __syncthreads();
    for (int s = 64; s > 0; s >>= 1) { if (tid < s) red[tid] = fmaxf(red[tid], red[tid + s]); __syncthreads(); }
    m0 = red[0]; __syncthreads();
    red[tid] = m1; __syncthreads();
    for (int s = 64; s > 0; s >>= 1) { if (tid < s) red[tid] = fmaxf(red[tid], red[tid + s]); __syncthreads(); }
    m1 = red[0]; __syncthreads();
    float z0 = 0.f, z1 = 0.f;
    for (int i = tid; i < deg; i += 128) {
        int eid = g_csr[beg + i];
        z0 += __expf(g_e[2 * eid] - m0);
        z1 += __expf(g_e[2 * eid + 1] - m1);
    }
    red[tid] = z0; __syncthreads();
    for (int s = 64; s > 0; s >>= 1) { if (tid < s) red[tid] += red[tid + s]; __syncthreads(); }
    z0 = red[0]; __syncthreads();
    red[tid] = z1; __syncthreads();
    for (int s = 64; s > 0; s >>= 1) { if (tid < s) red[tid] += red[tid + s]; __syncthreads(); }
    z1 = red[0]; __syncthreads();
    float acc = 0.f;
    int h = tid >> 6;
    for (int cs = 0; cs < deg; cs += 128) {
        int cnt = min(128, deg - cs);
        if (tid < cnt) {
            int eid = g_csr[beg + cs + tid];
            ssrc[tid] = src[eid];
            sw[0][tid] = __expf(g_e[2 * eid] - m0);
            sw[1][tid] = __expf(g_e[2 * eid + 1] - m1);
        }
        __syncthreads();
        for (int i = 0; i < cnt; i++)
            acc += g_Xn[(long)ssrc[i] * 128 + tid] * sw[h][i];
        __syncthreads();
    }
    g_agg[dn * 128 + tid] = acc / (h ? z1 : z0);
}

// ---------------- output assembly -------------------------------------------
__global__ void k_featcopy(const float* __restrict__ feat, float* __restrict__ out) {
    int i = blockIdx.x * 256 + threadIdx.x;
    if (i < NN * 32) {
        int r = i >> 5, c = i & 31;
        out[(long)r * 704 + c] = feat[i];
    }
}
__global__ void k_gmax_init() {
    int i = blockIdx.x * blockDim.x + threadIdx.x;
    if (i < 352) g_gmax[i] = fenc(-FLT_MAX);
}
__global__ void k_colmax(const float* __restrict__ out) {
    int col = blockIdx.y * 128 + threadIdx.x;
    if (col >= 352) return;
    int r0 = blockIdx.x * 512;
    int r1 = min(NN, r0 + 512);
    float m = -FLT_MAX;
    for (int r = r0; r < r1; r++) m = fmaxf(m, out[(long)r * 704 + col]);
    atomicMax(&g_gmax[col], fenc(m));
}
__global__ void k_bcast(float* __restrict__ out) {
    int i = blockIdx.x * 256 + threadIdx.x;
    if (i < NN * 352) {
        int r = i / 352, c = i - r * 352;
        out[(long)r * 704 + 352 + c] = fdec(g_gmax[c]);
    }
}

// ---------------- host driver ------------------------------------------------
extern "C" void kernel_launch(void* const* d_in, const int* in_sizes, int n_in,
                              void* d_out, int out_size) {
    const float* feat    = (const float*)d_in[0];
    const float* att_rc  = (const float*)d_in[1];
    const float* att_rp  = (const float*)d_in[2];
    const float* type_emb= (const float*)d_in[3];
    const float* rid_emb = (const float*)d_in[4];
    const float* rc_W    = (const float*)d_in[5];
    const float* rc_b    = (const float*)d_in[6];
    const float* rp_W    = (const float*)d_in[7];
    const float* rp_b    = (const float*)d_in[8];
    const float* fe_W1   = (const float*)d_in[9];
    const float* fe_b1   = (const float*)d_in[10];
    const float* fe_W2   = (const float*)d_in[11];
    const float* fe_b2   = (const float*)d_in[12];
    const float* W_ni    = (const float*)d_in[13];
    const float* W_nj    = (const float*)d_in[14];
    const float* W_fij   = (const float*)d_in[15];
    const float* W_node  = (const float*)d_in[16];
    const float* b_node  = (const float*)d_in[17];
    const float* attn    = (const float*)d_in[18];
    const float* mlp_W1  = (const float*)d_in[19];
    const float* mlp_b1  = (const float*)d_in[20];
    const float* mlp_W2  = (const float*)d_in[21];
    const float* mlp_b2  = (const float*)d_in[22];
    const int* src   = (const int*)d_in[23];
    const int* dst   = (const int*)d_in[24];
    const int* etype = (const int*)d_in[25];
    const int* erid  = (const int*)d_in[26];
    float* out = (float*)d_out;

    float *pXi, *pXj, *pXn, *pAgg, *pHid, *pHb;
    cudaGetSymbolAddress((void**)&pXi, g_Xi);
    cudaGetSymbolAddress((void**)&pXj, g_Xj);
    cudaGetSymbolAddress((void**)&pXn, g_Xn);
    cudaGetSymbolAddress((void**)&pAgg, g_agg);
    cudaGetSymbolAddress((void**)&pHid, g_hid);
    cudaGetSymbolAddress((void**)&pHb, g_hbuf);

    // CSR by dst
    k_csr_init<<<(NN + 255) / 256, 256>>>();
    k_hist<<<(EE + 255) / 256, 256>>>(dst);
    k_scan1<<<NB_SCAN, 512>>>();
    k_scan2<<<1, 32>>>();
    k_scan3<<<(NN + 255) / 256, 256>>>();
    k_scatter<<<(EE + 255) / 256, 256>>>(dst);

    // output cols [0,32) = feat
    k_featcopy<<<(NN * 32 + 255) / 256, 256>>>(feat, out);

    const int G64  = (NN + 127) / 128;  // BM=128 for BN=64 kernels
    const int G128 = (NN + 63) / 64;    // BM=64  for BN=128 kernels

    // feature-encoder MLP -> h0 (dense g_hbuf + out cols [32,96))
    k_gemm_t<128, 64><<<G64, 128>>>(feat, 32, fe_W1, fe_b1, nullptr, 0,
                                    pHid, 64, nullptr, 0, NN, 32, 1);
    k_gemm_t<128, 64><<<G64, 128>>>(pHid, 64, fe_W2, fe_b2, nullptr, 0,
                                    pHb, 64, out + 32, 704, NN, 64, 0);

    for (int l = 0; l < 4; l++) {
        k_gemm_t<64, 128><<<G128, 128>>>(pHb, 64, W_ni + l * 64 * 128, nullptr, nullptr, 0,
                                         pXi, 128, nullptr, 0, NN, 64, 0);
        k_gemm_t<64, 128><<<G128, 128>>>(pHb, 64, W_nj + l * 64 * 128, nullptr, nullptr, 0,
                                         pXj, 128, nullptr, 0, NN, 64, 0);
        k_gemm_t<64, 128><<<G128, 128>>>(pHb, 64, W_node + l * 64 * 128, b_node + l * 128, nullptr, 0,
                                         pXn, 128, nullptr, 0, NN, 64, 0);
        k_tables<<<1, 128>>>(type_emb, rid_emb, rc_W, rc_b, rp_W, rp_b, W_fij + l * 64 * 128);
        k_edge<<<2048, 256>>>(src, dst, etype, erid, att_rc, att_rp, attn + l * 128);
        k_agg<<<NN, 128>>>(src);
        k_gemm_t<64, 128><<<G128, 128>>>(pAgg, 128, mlp_W1 + l * 128 * 128, mlp_b1 + l * 128, nullptr, 0,
                                         pHid, 128, nullptr, 0, NN, 128, 1);
        // h_{l+1} = hid @ mlp_W2 + b2 + h_l  -> g_hbuf (overwrite) + out cols
        k_gemm_t<128, 64><<<G64, 128>>>(pHid, 128, mlp_W2 + l * 128 * 64, mlp_b2 + l * 64, pHb, 64,
                                        pHb, 64, out + 32 + 64 * (l + 1), 704, NN, 128, 0);
    }

    // graph max pooling over node_emb (cols [0,352)) -> broadcast to cols [352,704)
    k_gmax_init<<<2, 256>>>();
    dim3 gcm((NN + 511) / 512, 3);
    k_colmax<<<gcm, 128>>>(out);
    k_bcast<<<(NN * 352 + 255) / 256, 256>>>(out);
}